// round 6
// baseline (speedup 1.0000x reference)
#include <cuda_runtime.h>

#define BATCH 32
#define DIM 96
#define HH 128
#define WW 128
#define CR 24            // DIM / 4
#define KK 9             // 3x3
#define PLANE_ELEMS (HH * WW)          // 16384
#define PLANE_F4 (PLANE_ELEMS / 4)     // 4096
#define NPLANES (BATCH * DIM)          // 3072
#define BN_EPS 1e-5f

// scratch (no allocations allowed)
__device__ float g_pooled[NPLANES];          // [b][c] mean

// ---------------------------------------------------------------------------
// Kernel 1: global average pool per (b,c) plane. One block per plane.
// 81% DRAM — at ceiling; unchanged. Ascending order warms L2 tail for dwconv.
// ---------------------------------------------------------------------------
__global__ void pool_kernel(const float* __restrict__ x) {
    const int plane = blockIdx.x;
    const float4* __restrict__ x4 = (const float4*)(x) + (size_t)plane * PLANE_F4;
    const int tid = threadIdx.x;

    float acc = 0.f;
#pragma unroll 4
    for (int i = tid; i < PLANE_F4; i += 256) {
        float4 v = x4[i];
        acc += (v.x + v.y) + (v.z + v.w);
    }
#pragma unroll
    for (int off = 16; off > 0; off >>= 1)
        acc += __shfl_xor_sync(0xffffffffu, acc, off);

    __shared__ float warp_sums[8];
    if ((tid & 31) == 0) warp_sums[tid >> 5] = acc;
    __syncthreads();
    if (tid == 0) {
        float s = 0.f;
#pragma unroll
        for (int w = 0; w < 8; w++) s += warp_sums[w];
        g_pooled[plane] = s * (1.0f / (float)PLANE_ELEMS);
    }
}

// ---------------------------------------------------------------------------
// Kernel 2: fused weight-gen + depthwise 3x3 (stride 1, pad 1).
// One 256-thread block per 4 consecutive planes (same sample). The block
// recomputes h1 + its 36 filter taps (cheap, redundant across the sample's
// 24 blocks), then 8 warps each convolve a 64-row chunk of one plane with a
// register sliding window fed by coalesced LDG.128 (__ldcs). Column halo via
// SHFL; lane 0/31 edges are the true zero pad. Planes processed in REVERSE
// order so the tail of x (L2-resident after pool) is read as hits.
// ---------------------------------------------------------------------------
__global__ __launch_bounds__(256) void dwconv_kernel(const float* __restrict__ x,
                                                     const float* __restrict__ w1,
                                                     const float* __restrict__ gamma,
                                                     const float* __restrict__ beta,
                                                     const float* __restrict__ rmean,
                                                     const float* __restrict__ rvar,
                                                     const float* __restrict__ w2,
                                                     const float* __restrict__ b2,
                                                     const float* __restrict__ bias,
                                                     float* __restrict__ out) {
    const int base_plane = (NPLANES - 4) - 4 * blockIdx.x;  // reversed
    const int sample = base_plane / DIM;
    const int tid = threadIdx.x;

    __shared__ float h1_s[CR];
    __shared__ float wsh[4][KK];
    __shared__ float bsh[4];

    // h1 = sigmoid(BN(pooled @ w1^T))   (threads 0..23)
    if (tid < CR) {
        const float* pp = g_pooled + sample * DIM;
        const float* wrow = w1 + tid * DIM;
        float acc = 0.f;
#pragma unroll 8
        for (int i = 0; i < DIM; i++) acc += pp[i] * wrow[i];
        float z = (acc - rmean[tid]) * rsqrtf(rvar[tid] + BN_EPS) * gamma[tid] + beta[tid];
        h1_s[tid] = 1.0f / (1.0f + __expf(-z));
    }
    __syncthreads();

    // filter taps for this block's 4 planes  (threads 0..35)
    if (tid < 4 * KK) {
        const int pl = tid / KK, o = tid % KK;
        const int c = (base_plane + pl) % DIM;
        const float* wrow = w2 + (c * KK + o) * CR;
        float acc = b2[c * KK + o];
#pragma unroll
        for (int i = 0; i < CR; i++) acc += h1_s[i] * wrow[i];
        wsh[pl][o] = acc;
    }
    if (tid >= 40 && tid < 44) bsh[tid - 40] = bias[(base_plane + tid - 40) % DIM];
    __syncthreads();

    // conv: warp w -> plane base+ (w>>1), 64-row chunk (w&1)
    const int w  = tid >> 5;
    const int tx = tid & 31;
    const int pl = w >> 1;
    const int r0 = (w & 1) * 64;
    const int plane = base_plane + pl;

    const float4* __restrict__ x4   = (const float4*)(x) + (size_t)plane * PLANE_F4;
    float4*       __restrict__ out4 = (float4*)(out)     + (size_t)plane * PLANE_F4;

    const float w00 = wsh[pl][0], w01 = wsh[pl][1], w02 = wsh[pl][2];
    const float w10 = wsh[pl][3], w11 = wsh[pl][4], w12 = wsh[pl][5];
    const float w20 = wsh[pl][6], w21 = wsh[pl][7], w22 = wsh[pl][8];
    const float bv = bsh[pl];

    const float4 zero4 = make_float4(0.f, 0.f, 0.f, 0.f);

    // sliding window rows A=r-1, B=r, C=r+1
    float4 vA = (r0 == 0) ? zero4 : __ldcs(&x4[(r0 - 1) * 32 + tx]);
    float4 vB = __ldcs(&x4[r0 * 32 + tx]);
    float lA = __shfl_up_sync(0xffffffffu, vA.w, 1);
    float rA = __shfl_down_sync(0xffffffffu, vA.x, 1);
    float lB = __shfl_up_sync(0xffffffffu, vB.w, 1);
    float rB = __shfl_down_sync(0xffffffffu, vB.x, 1);
    if (tx == 0)  { lA = 0.f; lB = 0.f; }
    if (tx == 31) { rA = 0.f; rB = 0.f; }

#pragma unroll 4
    for (int i = 0; i < 64; i++) {
        const int rn = r0 + i + 1;
        float4 vC = (rn < HH) ? __ldcs(&x4[rn * 32 + tx]) : zero4;
        float lC = __shfl_up_sync(0xffffffffu, vC.w, 1);
        float rC = __shfl_down_sync(0xffffffffu, vC.x, 1);
        if (tx == 0)  lC = 0.f;
        if (tx == 31) rC = 0.f;

        float4 o;
        o.x = bv + w00 * lA   + w01 * vA.x + w02 * vA.y
                 + w10 * lB   + w11 * vB.x + w12 * vB.y
                 + w20 * lC   + w21 * vC.x + w22 * vC.y;
        o.y = bv + w00 * vA.x + w01 * vA.y + w02 * vA.z
                 + w10 * vB.x + w11 * vB.y + w12 * vB.z
                 + w20 * vC.x + w21 * vC.y + w22 * vC.z;
        o.z = bv + w00 * vA.y + w01 * vA.z + w02 * vA.w
                 + w10 * vB.y + w11 * vB.z + w12 * vB.w
                 + w20 * vC.y + w21 * vC.z + w22 * vC.w;
        o.w = bv + w00 * vA.z + w01 * vA.w + w02 * rA
                 + w10 * vB.z + w11 * vB.w + w12 * rB
                 + w20 * vC.z + w21 * vC.w + w22 * rC;

        out4[(r0 + i) * 32 + tx] = o;

        vA = vB; lA = lB; rA = rB;
        vB = vC; lB = lC; rB = rC;
    }
}

// ---------------------------------------------------------------------------
extern "C" void kernel_launch(void* const* d_in, const int* in_sizes, int n_in,
                              void* d_out, int out_size) {
    const float* x     = (const float*)d_in[0];
    const float* w1    = (const float*)d_in[1];
    const float* gamma = (const float*)d_in[2];
    const float* beta  = (const float*)d_in[3];
    const float* rmean = (const float*)d_in[4];
    const float* rvar  = (const float*)d_in[5];
    const float* w2    = (const float*)d_in[6];
    const float* b2    = (const float*)d_in[7];
    const float* bias  = (const float*)d_in[8];
    float* out = (float*)d_out;

    pool_kernel<<<NPLANES, 256>>>(x);
    dwconv_kernel<<<NPLANES / 4, 256>>>(x, w1, gamma, beta, rmean, rvar,
                                        w2, b2, bias, out);
}

// round 7
// speedup vs baseline: 1.1139x; 1.1139x over previous
#include <cuda_runtime.h>

#define BATCH 32
#define DIM 96
#define HH 128
#define WW 128
#define CR 24            // DIM / 4
#define KK 9             // 3x3
#define PLANE_ELEMS (HH * WW)          // 16384
#define PLANE_F4 (PLANE_ELEMS / 4)     // 4096
#define PLANE_BYTES (PLANE_ELEMS * 4)  // 65536
#define NPLANES (BATCH * DIM)          // 3072
#define BN_EPS 1e-5f

// scratch (no allocations allowed)
__device__ float g_pooled[NPLANES];
__device__ int   g_cnt[BATCH];

__global__ void init_kernel() {
    if (threadIdx.x < BATCH) g_cnt[threadIdx.x] = 0;
}

// ---------------------------------------------------------------------------
// Fused kernel: one block per (b,c) plane.
//   load plane -> smem (+pool sum on the fly) -> publish pooled -> wait for
//   sample's 96 pools -> weight gen (redundant, tiny) -> conv from smem.
// x is read from DRAM exactly once.
// ---------------------------------------------------------------------------
__global__ __launch_bounds__(256) void fused_kernel(const float* __restrict__ x,
                                                    const float* __restrict__ w1,
                                                    const float* __restrict__ gamma,
                                                    const float* __restrict__ beta,
                                                    const float* __restrict__ rmean,
                                                    const float* __restrict__ rvar,
                                                    const float* __restrict__ w2,
                                                    const float* __restrict__ b2,
                                                    const float* __restrict__ bias,
                                                    float* __restrict__ out) {
    extern __shared__ float4 s4[];               // PLANE_F4 float4 = 64 KB
    __shared__ float warp_sums[8];
    __shared__ float pooled_s[DIM];
    __shared__ float h1_s[CR];
    __shared__ float wsh[KK];
    __shared__ float bsh;

    const int plane  = blockIdx.x;
    const int sample = plane / DIM;
    const int c      = plane % DIM;
    const int tid    = threadIdx.x;

    // ---- 1. load plane to smem, accumulate pool sum ----
    const float4* __restrict__ x4 = (const float4*)(x) + (size_t)plane * PLANE_F4;
    float acc = 0.f;
#pragma unroll
    for (int i = 0; i < 16; i++) {
        const int idx = tid + 256 * i;
        float4 v = x4[idx];
        s4[idx] = v;
        acc += (v.x + v.y) + (v.z + v.w);
    }
#pragma unroll
    for (int off = 16; off > 0; off >>= 1)
        acc += __shfl_xor_sync(0xffffffffu, acc, off);
    if ((tid & 31) == 0) warp_sums[tid >> 5] = acc;
    __syncthreads();

    // ---- 2. publish pooled mean ----
    if (tid == 0) {
        float s = 0.f;
#pragma unroll
        for (int w = 0; w < 8; w++) s += warp_sums[w];
        g_pooled[plane] = s * (1.0f / (float)PLANE_ELEMS);
        __threadfence();
        atomicAdd(&g_cnt[sample], 1);
    }

    // ---- 3. wait for all 96 pools of this sample ----
    if (tid == 0) {
        volatile int* cnt = &g_cnt[sample];
        while (*cnt < DIM) __nanosleep(64);
    }
    __syncthreads();

    // ---- 4. weight generation (redundant per block; tiny) ----
    if (tid < DIM) pooled_s[tid] = __ldcg(&g_pooled[sample * DIM + tid]);
    __syncthreads();

    if (tid < CR) {
        const float* wrow = w1 + tid * DIM;
        float a = 0.f;
#pragma unroll 8
        for (int i = 0; i < DIM; i++) a += pooled_s[i] * wrow[i];
        float z = (a - rmean[tid]) * rsqrtf(rvar[tid] + BN_EPS) * gamma[tid] + beta[tid];
        h1_s[tid] = 1.0f / (1.0f + __expf(-z));
    }
    __syncthreads();

    if (tid < KK) {
        const float* wrow = w2 + (c * KK + tid) * CR;
        float a = b2[c * KK + tid];
#pragma unroll
        for (int i = 0; i < CR; i++) a += h1_s[i] * wrow[i];
        wsh[tid] = a;
    }
    if (tid == KK) bsh = bias[c];
    __syncthreads();

    // ---- 5. convolve from smem (reg sliding window + SHFL col halo) ----
    const float w00 = wsh[0], w01 = wsh[1], w02 = wsh[2];
    const float w10 = wsh[3], w11 = wsh[4], w12 = wsh[5];
    const float w20 = wsh[6], w21 = wsh[7], w22 = wsh[8];
    const float bv = bsh;

    const int w  = tid >> 5;      // warp 0..7 -> 16-row band
    const int tx = tid & 31;
    const int r0 = w * 16;

    float4* __restrict__ out4 = (float4*)(out) + (size_t)plane * PLANE_F4;
    const float4 zero4 = make_float4(0.f, 0.f, 0.f, 0.f);

    float4 vA = (r0 == 0) ? zero4 : s4[(r0 - 1) * 32 + tx];
    float4 vB = s4[r0 * 32 + tx];
    float lA = __shfl_up_sync(0xffffffffu, vA.w, 1);
    float rA = __shfl_down_sync(0xffffffffu, vA.x, 1);
    float lB = __shfl_up_sync(0xffffffffu, vB.w, 1);
    float rB = __shfl_down_sync(0xffffffffu, vB.x, 1);
    if (tx == 0)  { lA = 0.f; lB = 0.f; }
    if (tx == 31) { rA = 0.f; rB = 0.f; }

#pragma unroll 4
    for (int i = 0; i < 16; i++) {
        const int rn = r0 + i + 1;
        float4 vC = (rn < HH) ? s4[rn * 32 + tx] : zero4;
        float lC = __shfl_up_sync(0xffffffffu, vC.w, 1);
        float rC = __shfl_down_sync(0xffffffffu, vC.x, 1);
        if (tx == 0)  lC = 0.f;
        if (tx == 31) rC = 0.f;

        float4 o;
        o.x = bv + w00 * lA   + w01 * vA.x + w02 * vA.y
                 + w10 * lB   + w11 * vB.x + w12 * vB.y
                 + w20 * lC   + w21 * vC.x + w22 * vC.y;
        o.y = bv + w00 * vA.x + w01 * vA.y + w02 * vA.z
                 + w10 * vB.x + w11 * vB.y + w12 * vB.z
                 + w20 * vC.x + w21 * vC.y + w22 * vC.z;
        o.z = bv + w00 * vA.y + w01 * vA.z + w02 * vA.w
                 + w10 * vB.y + w11 * vB.z + w12 * vB.w
                 + w20 * vC.y + w21 * vC.z + w22 * vC.w;
        o.w = bv + w00 * vA.z + w01 * vA.w + w02 * rA
                 + w10 * vB.z + w11 * vB.w + w12 * rB
                 + w20 * vC.z + w21 * vC.w + w22 * rC;

        out4[(r0 + i) * 32 + tx] = o;

        vA = vB; lA = lB; rA = rB;
        vB = vC; lB = lC; rB = rC;
    }
}

// ---------------------------------------------------------------------------
extern "C" void kernel_launch(void* const* d_in, const int* in_sizes, int n_in,
                              void* d_out, int out_size) {
    const float* x     = (const float*)d_in[0];
    const float* w1    = (const float*)d_in[1];
    const float* gamma = (const float*)d_in[2];
    const float* beta  = (const float*)d_in[3];
    const float* rmean = (const float*)d_in[4];
    const float* rvar  = (const float*)d_in[5];
    const float* w2    = (const float*)d_in[6];
    const float* b2    = (const float*)d_in[7];
    const float* bias  = (const float*)d_in[8];
    float* out = (float*)d_out;

    static int configured = 0;
    if (!configured) {
        cudaFuncSetAttribute(fused_kernel,
                             cudaFuncAttributeMaxDynamicSharedMemorySize,
                             PLANE_BYTES);
        configured = 1;
    }

    init_kernel<<<1, 32>>>();
    fused_kernel<<<NPLANES, 256, PLANE_BYTES>>>(x, w1, gamma, beta, rmean, rvar,
                                                w2, b2, bias, out);
}